// round 14
// baseline (speedup 1.0000x reference)
#include <cuda_runtime.h>
#include <cuda_bf16.h>
#include <math.h>
#include <stdint.h>

#define N_NODES 20000
#define E_EDGES 320000
#define F_IN    1024
#define H_MID   256
#define D_OUT   128
#define QKVS    512
#define STAT_BLOCKS 256
#define M_TILES ((N_NODES + 127) / 128)

// ---------------- scratch (static device globals; no allocations) ----------------
// zero-initialized at module load; g_degcnt/g_fill self-reset across graph replays.
__device__ __align__(16) float  g_g[(size_t)N_NODES * H_MID];
__device__ __align__(16) float  g_qkvs[(size_t)N_NODES * QKVS];
__device__ __align__(16) float  g_alpha[E_EDGES];
__device__ float  g_dinv[N_NODES];
__device__ int    g_degcnt[N_NODES];
__device__ int    g_fill[N_NODES];
__device__ int    g_rowptr[N_NODES + 1];
__device__ int    g_csrc[E_EDGES];
__device__ int    g_ceid[E_EDGES];
__device__ double g_part[STAT_BLOCKS][2];
__device__ float  g_stats[2];
__device__ __align__(16) float  g_bcat[QKVS];
// bf16 split operands
__device__ __align__(16) __nv_bfloat16 g_B1hi[(size_t)H_MID * F_IN];   // W_gcn^T [256][1024]
__device__ __align__(16) __nv_bfloat16 g_B1lo[(size_t)H_MID * F_IN];
__device__ __align__(16) __nv_bfloat16 g_Hhi[(size_t)N_NODES * H_MID]; // split h
__device__ __align__(16) __nv_bfloat16 g_Hlo[(size_t)N_NODES * H_MID];
__device__ __align__(16) __nv_bfloat16 g_B2hi[(size_t)QKVS * H_MID];   // Wcat^T [512][256]
__device__ __align__(16) __nv_bfloat16 g_B2lo[(size_t)QKVS * H_MID];

// ---------------- helpers ----------------
__device__ __forceinline__ uint32_t smem_u32(const void* p) {
    uint32_t a;
    asm("{ .reg .u64 t; cvta.to.shared.u64 t, %1; cvt.u32.u64 %0, t; }" : "=r"(a) : "l"(p));
    return a;
}
__device__ __forceinline__ void mma16816(float* c, const uint32_t* a, const uint32_t* b) {
    asm volatile(
        "mma.sync.aligned.m16n8k16.row.col.f32.bf16.bf16.f32 "
        "{%0,%1,%2,%3}, {%4,%5,%6,%7}, {%8,%9}, {%0,%1,%2,%3};"
        : "+f"(c[0]), "+f"(c[1]), "+f"(c[2]), "+f"(c[3])
        : "r"(a[0]), "r"(a[1]), "r"(a[2]), "r"(a[3]), "r"(b[0]), "r"(b[1]));
}
__device__ __forceinline__ void ldm4(uint32_t* r, uint32_t addr) {
    asm volatile("ldmatrix.sync.aligned.m8n8.x4.shared.b16 {%0,%1,%2,%3}, [%4];"
        : "=r"(r[0]), "=r"(r[1]), "=r"(r[2]), "=r"(r[3]) : "r"(addr) : "memory");
}
__device__ __forceinline__ void split2(float a, float b, __nv_bfloat162& h, __nv_bfloat162& l) {
    __nv_bfloat16 ha = __float2bfloat16_rn(a);
    __nv_bfloat16 hb = __float2bfloat16_rn(b);
    h.x = ha; h.y = hb;
    l.x = __float2bfloat16_rn(a - __bfloat162float(ha));
    l.y = __float2bfloat16_rn(b - __bfloat162float(hb));
}
__device__ __forceinline__ void splitpack(float a, float b, uint32_t& hw, uint32_t& lw) {
    __nv_bfloat162 h, l;
    split2(a, b, h, l);
    hw = *(uint32_t*)&h;
    lw = *(uint32_t*)&l;
}

// ---------------- merged: W_gcn conversion + degree histogram ----------------
__global__ void k_convBW_hist(const float* __restrict__ Wg, const int* __restrict__ ei) {
    int idx = blockIdx.x * blockDim.x + threadIdx.x;
    if (idx < H_MID * F_IN) {
        int n = idx >> 10, k = idx & 1023;
        float v = Wg[(size_t)k * H_MID + n];
        __nv_bfloat16 h = __float2bfloat16_rn(v);
        g_B1hi[idx] = h;
        g_B1lo[idx] = __float2bfloat16_rn(v - __bfloat162float(h));
    }
    if (idx < E_EDGES) atomicAdd(&g_degcnt[ei[E_EDGES + idx]], 1);
}

// single-block scan; computes dinv; self-resets degcnt
__global__ void k_scan() {
    const int n = N_NODES;
    const int PER = 20;
    __shared__ int wsum[32];
    int tid = threadIdx.x, lane = tid & 31, wid = tid >> 5;
    int start = tid * PER;
    int cnt[PER];
    int local = 0;
#pragma unroll
    for (int u = 0; u < PER; u++) {
        int i = start + u;
        int c = (i < n) ? g_degcnt[i] : 0;
        cnt[u] = c; local += c;
        if (i < n) g_degcnt[i] = 0;
    }
    int v = local;
#pragma unroll
    for (int d = 1; d < 32; d <<= 1) { int t = __shfl_up_sync(0xffffffffu, v, d); if (lane >= d) v += t; }
    if (lane == 31) wsum[wid] = v;
    __syncthreads();
    if (wid == 0) {
        int w = wsum[lane];
#pragma unroll
        for (int d = 1; d < 32; d <<= 1) { int t = __shfl_up_sync(0xffffffffu, w, d); if (lane >= d) w += t; }
        wsum[lane] = w;
    }
    __syncthreads();
    int excl = (v - local) + (wid > 0 ? wsum[wid - 1] : 0);
    int run = excl;
#pragma unroll
    for (int u = 0; u < PER; u++) {
        int i = start + u;
        if (i < n) {
            g_rowptr[i] = run;
            g_dinv[i] = rsqrtf((float)(cnt[u] + 1));
        }
        run += cnt[u];
    }
    if (tid == 1023) g_rowptr[n] = run;
}

// ---------------- merged: QKVS weight pack + CSR scatter ----------------
__global__ void k_packB2_csr(const float* __restrict__ Wq, const float* __restrict__ Wk,
                             const float* __restrict__ Wv, const float* __restrict__ Ws,
                             const float* __restrict__ bq, const float* __restrict__ bk,
                             const float* __restrict__ bv, const float* __restrict__ bs,
                             const int* __restrict__ ei) {
    int idx = blockIdx.x * blockDim.x + threadIdx.x;
    if (idx < QKVS * H_MID) {
        int n = idx >> 8, k = idx & 255;
        int w = n >> 7, c = n & 127;
        const float* W = (w == 0) ? Wq : (w == 1) ? Wk : (w == 2) ? Wv : Ws;
        float v = W[(size_t)k * D_OUT + c];
        __nv_bfloat16 h = __float2bfloat16_rn(v);
        g_B2hi[idx] = h;
        g_B2lo[idx] = __float2bfloat16_rn(v - __bfloat162float(h));
        if (idx < QKVS) {
            int nn = idx, ww = nn >> 7, cc = nn & 127;
            const float* b = (ww == 0) ? bq : (ww == 1) ? bk : (ww == 2) ? bv : bs;
            g_bcat[nn] = b[cc];
        }
    }
    if (idx < E_EDGES) {
        int s = ei[idx];
        int d = ei[E_EDGES + idx];
        int pos = g_rowptr[d] + atomicAdd(&g_fill[d], 1);
        g_csrc[pos] = s;
        g_ceid[pos] = idx;
    }
}

// ---------------- split-bf16 GEMM: 128x128 tile, prefetch distance 2 ----------------
// MODE 0: g_g = (x @ W_gcn) * dinv[row]; A = fp32 x split in store phase; grid (157,2)
// MODE 1: g_qkvs = h @ Wcat + bcat; A = g_Hhi/Hlo; grid (157,4)
#define SPAD 24

template <int MODE>
__global__ __launch_bounds__(256)
void k_mmagemm(const float* __restrict__ X) {
    const int K_TOT = (MODE == 0) ? F_IN : H_MID;
    const __nv_bfloat16* Bhi = (MODE == 0) ? g_B1hi : g_B2hi;
    const __nv_bfloat16* Blo = (MODE == 0) ? g_B1lo : g_B2lo;

    __shared__ __align__(16) __nv_bfloat16 sAh[128 * SPAD], sAl[128 * SPAD];
    __shared__ __align__(16) __nv_bfloat16 sBh[128 * SPAD], sBl[128 * SPAD];

    int tid = threadIdx.x, wid = tid >> 5, lane = tid & 31;
    int m0 = blockIdx.x * 128, n0 = blockIdx.y * 128;
    int wm = wid & 3, wn = wid >> 2;          // warp grid 4(m) x 2(n); warp tile 32x64

    int lrow = tid >> 1, lhalf = (tid & 1) << 3;
    const int NCH = K_TOT / 16;
    int arow = m0 + lrow;
    bool aok = arow < N_NODES;
    const float* pX = X + (size_t)arow * K_TOT + lhalf;               // MODE 0
    const __nv_bfloat16* pAh = g_Hhi + (size_t)arow * K_TOT + lhalf;  // MODE 1
    const __nv_bfloat16* pAl = g_Hlo + (size_t)arow * K_TOT + lhalf;
    const __nv_bfloat16* pBh = Bhi + (size_t)(n0 + lrow) * K_TOT + lhalf;
    const __nv_bfloat16* pBl = Blo + (size_t)(n0 + lrow) * K_TOT + lhalf;

    // two register prefetch sets (distance 2)
    uint4 z4 = make_uint4(0, 0, 0, 0);
    float4 z4f = make_float4(0.f, 0.f, 0.f, 0.f);
    float4 xa[2] = {z4f, z4f}, xb[2] = {z4f, z4f};   // MODE 0
    uint4 vah[2] = {z4, z4}, val_[2] = {z4, z4};     // MODE 1
    uint4 vbh[2] = {z4, z4}, vbl[2] = {z4, z4};

    auto preload = [&](int c, int setx) {
        int k0 = c * 16;
        if (MODE == 0) {
            if (aok) { xa[setx] = *(const float4*)(pX + k0); xb[setx] = *(const float4*)(pX + k0 + 4); }
        } else {
            if (aok) { vah[setx] = *(const uint4*)(pAh + k0); val_[setx] = *(const uint4*)(pAl + k0); }
        }
        vbh[setx] = *(const uint4*)(pBh + k0);
        vbl[setx] = *(const uint4*)(pBl + k0);
    };

    preload(0, 0);
    preload(1, 1);

    float acc[2][8][4];
#pragma unroll
    for (int a = 0; a < 2; a++)
#pragma unroll
        for (int b = 0; b < 8; b++)
#pragma unroll
            for (int c = 0; c < 4; c++) acc[a][b][c] = 0.f;

    uint32_t baseAh = smem_u32(sAh), baseAl = smem_u32(sAl);
    uint32_t baseBh = smem_u32(sBh), baseBl = smem_u32(sBl);
    int soff = lrow * SPAD + lhalf;

    int g8 = lane >> 3, w8 = lane & 7;
    uint32_t a_off = (uint32_t)((((((g8 & 1) << 3) + w8) + wm * 32) * SPAD + ((g8 >> 1) << 3)) * 2);
    uint32_t b_off = (uint32_t)((((((g8 >> 1) << 3) + w8) + wn * 64) * SPAD + ((g8 & 1) << 3)) * 2);

    for (int c = 0; c < NCH; c++) {
        int sx = c & 1;
        // ---- store phase (data requested 2 chunks ago) ----
        if (MODE == 0) {
            uint4 hw, lw;
            splitpack(xa[sx].x, xa[sx].y, hw.x, lw.x);
            splitpack(xa[sx].z, xa[sx].w, hw.y, lw.y);
            splitpack(xb[sx].x, xb[sx].y, hw.z, lw.z);
            splitpack(xb[sx].z, xb[sx].w, hw.w, lw.w);
            *(uint4*)&sAh[soff] = hw;
            *(uint4*)&sAl[soff] = lw;
        } else {
            *(uint4*)&sAh[soff] = vah[sx];
            *(uint4*)&sAl[soff] = val_[sx];
        }
        *(uint4*)&sBh[soff] = vbh[sx];
        *(uint4*)&sBl[soff] = vbl[sx];
        __syncthreads();
        // ---- issue loads for chunk c+2 into the set just freed ----
        if (c + 2 < NCH) preload(c + 2, sx);

        uint32_t ah[2][4], al[2][4], bh[4][4], bl[4][4];
#pragma unroll
        for (int mb = 0; mb < 2; mb++) {
            ldm4(ah[mb], baseAh + a_off + mb * 16 * SPAD * 2);
            ldm4(al[mb], baseAl + a_off + mb * 16 * SPAD * 2);
        }
#pragma unroll
        for (int q = 0; q < 4; q++) {
            ldm4(bh[q], baseBh + b_off + q * 16 * SPAD * 2);
            ldm4(bl[q], baseBl + b_off + q * 16 * SPAD * 2);
        }
#pragma unroll
        for (int mb = 0; mb < 2; mb++)
#pragma unroll
            for (int q = 0; q < 4; q++)
#pragma unroll
                for (int hh = 0; hh < 2; hh++) {
                    float* ca = acc[mb][q * 2 + hh];
                    mma16816(ca, ah[mb], &bh[q][hh * 2]);
                    mma16816(ca, al[mb], &bh[q][hh * 2]);
                    mma16816(ca, ah[mb], &bl[q][hh * 2]);
                }
        __syncthreads();
    }

    const int CS = (MODE == 0) ? H_MID : QKVS;
    float* Cp = (MODE == 0) ? g_g : g_qkvs;
#pragma unroll
    for (int mb = 0; mb < 2; mb++) {
        int rbase = m0 + wm * 32 + mb * 16 + (lane >> 2);
#pragma unroll
        for (int hf = 0; hf < 2; hf++) {
            int r = rbase + hf * 8;
            if (r >= N_NODES) continue;
            float rs = (MODE == 0) ? g_dinv[r] : 1.f;
#pragma unroll
            for (int n8 = 0; n8 < 8; n8++) {
                int col = n0 + wn * 64 + n8 * 8 + ((lane & 3) << 1);
                float v0 = acc[mb][n8][hf * 2 + 0];
                float v1 = acc[mb][n8][hf * 2 + 1];
                if (MODE == 0) { v0 *= rs; v1 *= rs; }
                else { v0 += g_bcat[col]; v1 += g_bcat[col + 1]; }
                float2 o; o.x = v0; o.y = v1;
                *(float2*)(Cp + (size_t)r * CS + col) = o;
            }
        }
    }
}

// ---------------- GCN aggregation: float2/thread, 8-way unroll, split write ----------------
__global__ __launch_bounds__(128)
void k_agg(const float* __restrict__ b_gcn) {
    int i = blockIdx.x;
    int f = threadIdx.x;
    if (f == 0) g_fill[i] = 0;                 // reset for next replay
    const float2* G = (const float2*)g_g;
    float2 a0 = G[(size_t)i * 128 + f];        // self loop
    float2 a1 = make_float2(0.f, 0.f), a2 = a1, a3 = a1;
    float2 a4 = a1, a5 = a1, a6 = a1, a7 = a1;
    __shared__ int sj[128];
    int s0 = g_rowptr[i], e0 = g_rowptr[i + 1];
    for (int base = s0; base < e0; base += 128) {
        int cnt = min(128, e0 - base);
        if (f < cnt) sj[f] = g_csrc[base + f];
        __syncthreads();
        int p = 0;
        for (; p + 8 <= cnt; p += 8) {
            float2 v0 = G[(size_t)sj[p + 0] * 128 + f];
            float2 v1 = G[(size_t)sj[p + 1] * 128 + f];
            float2 v2 = G[(size_t)sj[p + 2] * 128 + f];
            float2 v3 = G[(size_t)sj[p + 3] * 128 + f];
            float2 v4 = G[(size_t)sj[p + 4] * 128 + f];
            float2 v5 = G[(size_t)sj[p + 5] * 128 + f];
            float2 v6 = G[(size_t)sj[p + 6] * 128 + f];
            float2 v7 = G[(size_t)sj[p + 7] * 128 + f];
            a0.x += v0.x; a0.y += v0.y;
            a1.x += v1.x; a1.y += v1.y;
            a2.x += v2.x; a2.y += v2.y;
            a3.x += v3.x; a3.y += v3.y;
            a4.x += v4.x; a4.y += v4.y;
            a5.x += v5.x; a5.y += v5.y;
            a6.x += v6.x; a6.y += v6.y;
            a7.x += v7.x; a7.y += v7.y;
        }
        for (; p + 4 <= cnt; p += 4) {
            float2 v0 = G[(size_t)sj[p + 0] * 128 + f];
            float2 v1 = G[(size_t)sj[p + 1] * 128 + f];
            float2 v2 = G[(size_t)sj[p + 2] * 128 + f];
            float2 v3 = G[(size_t)sj[p + 3] * 128 + f];
            a0.x += v0.x; a0.y += v0.y;
            a1.x += v1.x; a1.y += v1.y;
            a2.x += v2.x; a2.y += v2.y;
            a3.x += v3.x; a3.y += v3.y;
        }
        for (; p < cnt; p++) {
            float2 v = G[(size_t)sj[p] * 128 + f];
            a0.x += v.x; a0.y += v.y;
        }
        __syncthreads();
    }
    float di = g_dinv[i];
    float2 bb = ((const float2*)b_gcn)[f];
    float vx = di * (((a0.x + a1.x) + (a2.x + a3.x)) + ((a4.x + a5.x) + (a6.x + a7.x))) + bb.x;
    float vy = di * (((a0.y + a1.y) + (a2.y + a3.y)) + ((a4.y + a5.y) + (a6.y + a7.y))) + bb.y;
    vx = (vx >= 0.f) ? vx : 0.01f * vx;
    vy = (vy >= 0.f) ? vy : 0.01f * vy;
    __nv_bfloat162 h, l;
    split2(vx, vy, h, l);
    ((__nv_bfloat162*)g_Hhi)[(size_t)i * 128 + f] = h;
    ((__nv_bfloat162*)g_Hlo)[(size_t)i * 128 + f] = l;
}

// ---------------- attention logits (warp per edge) ----------------
__global__ __launch_bounds__(256)
void k_alpha(const int* __restrict__ ei) {
    int warp = threadIdx.x >> 5, lane = threadIdx.x & 31;
    int e = blockIdx.x * 8 + warp;
    if (e >= E_EDGES) return;
    int s = ei[e], d = ei[E_EDGES + e];
    const float4* q = (const float4*)(g_qkvs + (size_t)d * QKVS);
    const float4* k = (const float4*)(g_qkvs + (size_t)s * QKVS + D_OUT);
    float4 a = q[lane], b = k[lane];
    float p = a.x * b.x + a.y * b.y + a.z * b.z + a.w * b.w;
#pragma unroll
    for (int o = 16; o; o >>= 1) p += __shfl_xor_sync(0xffffffffu, p, o);
    if (lane == 0) g_alpha[e] = p * 0.08838834764831845f;
}

__global__ __launch_bounds__(256)
void k_stats() {
    double s = 0.0, s2 = 0.0;
    for (int i = blockIdx.x * blockDim.x + threadIdx.x; i < E_EDGES; i += STAT_BLOCKS * 256) {
        double a = (double)g_alpha[i];
        s += a; s2 += a * a;
    }
#pragma unroll
    for (int o = 16; o; o >>= 1) {
        s  += __shfl_down_sync(0xffffffffu, s,  o);
        s2 += __shfl_down_sync(0xffffffffu, s2, o);
    }
    __shared__ double ws[8], ws2[8];
    int lane = threadIdx.x & 31, wid = threadIdx.x >> 5;
    if (lane == 0) { ws[wid] = s; ws2[wid] = s2; }
    __syncthreads();
    if (threadIdx.x == 0) {
        double ts = 0.0, ts2 = 0.0;
        for (int w = 0; w < 8; w++) { ts += ws[w]; ts2 += ws2[w]; }
        g_part[blockIdx.x][0] = ts;
        g_part[blockIdx.x][1] = ts2;
    }
}

__global__ __launch_bounds__(STAT_BLOCKS)
void k_finalize() {
    int t = threadIdx.x;
    double s = g_part[t][0], s2 = g_part[t][1];
#pragma unroll
    for (int o = 16; o; o >>= 1) {
        s  += __shfl_down_sync(0xffffffffu, s,  o);
        s2 += __shfl_down_sync(0xffffffffu, s2, o);
    }
    __shared__ double ws[8], ws2[8];
    int lane = t & 31, wid = t >> 5;
    if (lane == 0) { ws[wid] = s; ws2[wid] = s2; }
    __syncthreads();
    if (t == 0) {
        double ts = 0.0, ts2 = 0.0;
        for (int w = 0; w < STAT_BLOCKS / 32; w++) { ts += ws[w]; ts2 += ws2[w]; }
        double En = (double)E_EDGES;
        double mean = ts / En;
        double var = (ts2 - En * mean * mean) / (En - 1.0);   // ddof=1
        g_stats[0] = (float)mean;
        g_stats[1] = (float)(3.0 / sqrt(var));                // SCALE_PARAM/std
    }
}

// ---------------- output: 8-way MLP unroll ----------------
__global__ __launch_bounds__(D_OUT)
void k_out(float* __restrict__ out) {
    int i = blockIdx.x;
    int f = threadIdx.x;
    float mean = g_stats[0], sc = g_stats[1];
    float a0 = g_qkvs[(size_t)i * QKVS + 384 + f];   // skip s = h@Ws + bs
    float a1 = 0.f, a2 = 0.f, a3 = 0.f, a4 = 0.f, a5 = 0.f, a6 = 0.f, a7 = 0.f;
    __shared__ int   sj[D_OUT];
    __shared__ float sa[D_OUT];
    int s0 = g_rowptr[i], e0 = g_rowptr[i + 1];
    for (int base = s0; base < e0; base += D_OUT) {
        int cnt = min(D_OUT, e0 - base);
        if (f < cnt) {
            sj[f] = g_csrc[base + f];
            float a = (g_alpha[g_ceid[base + f]] - mean) * sc;
            sa[f] = 1.0f / (1.0f + expf(-a));
        }
        __syncthreads();
        int p = 0;
        for (; p + 8 <= cnt; p += 8) {
            float v0 = g_qkvs[(size_t)sj[p + 0] * QKVS + 256 + f];
            float v1 = g_qkvs[(size_t)sj[p + 1] * QKVS + 256 + f];
            float v2 = g_qkvs[(size_t)sj[p + 2] * QKVS + 256 + f];
            float v3 = g_qkvs[(size_t)sj[p + 3] * QKVS + 256 + f];
            float v4 = g_qkvs[(size_t)sj[p + 4] * QKVS + 256 + f];
            float v5 = g_qkvs[(size_t)sj[p + 5] * QKVS + 256 + f];
            float v6 = g_qkvs[(size_t)sj[p + 6] * QKVS + 256 + f];
            float v7 = g_qkvs[(size_t)sj[p + 7] * QKVS + 256 + f];
            a0 += v0 * sa[p + 0];
            a1 += v1 * sa[p + 1];
            a2 += v2 * sa[p + 2];
            a3 += v3 * sa[p + 3];
            a4 += v4 * sa[p + 4];
            a5 += v5 * sa[p + 5];
            a6 += v6 * sa[p + 6];
            a7 += v7 * sa[p + 7];
        }
        for (; p + 4 <= cnt; p += 4) {
            float v0 = g_qkvs[(size_t)sj[p + 0] * QKVS + 256 + f];
            float v1 = g_qkvs[(size_t)sj[p + 1] * QKVS + 256 + f];
            float v2 = g_qkvs[(size_t)sj[p + 2] * QKVS + 256 + f];
            float v3 = g_qkvs[(size_t)sj[p + 3] * QKVS + 256 + f];
            a0 += v0 * sa[p + 0];
            a1 += v1 * sa[p + 1];
            a2 += v2 * sa[p + 2];
            a3 += v3 * sa[p + 3];
        }
        for (; p < cnt; p++)
            a0 += g_qkvs[(size_t)sj[p] * QKVS + 256 + f] * sa[p];
        __syncthreads();
    }
    out[(size_t)i * D_OUT + f] = ((a0 + a1) + (a2 + a3)) + ((a4 + a5) + (a6 + a7));
}

// ---------------- launch ----------------
extern "C" void kernel_launch(void* const* d_in, const int* in_sizes, int n_in,
                              void* d_out, int out_size) {
    (void)in_sizes; (void)n_in; (void)out_size;
    const float* x     = (const float*)d_in[0];
    const int*   ei    = (const int*)d_in[1];
    const float* W_gcn = (const float*)d_in[2];
    const float* b_gcn = (const float*)d_in[3];
    const float* Wq = (const float*)d_in[4],  *bq = (const float*)d_in[5];
    const float* Wk = (const float*)d_in[6],  *bk = (const float*)d_in[7];
    const float* Wv = (const float*)d_in[8],  *bv = (const float*)d_in[9];
    const float* Ws = (const float*)d_in[10], *bs = (const float*)d_in[11];
    float* out = (float*)d_out;

    k_convBW_hist<<<(E_EDGES + 255) / 256, 256>>>(W_gcn, ei);
    k_scan<<<1, 1024>>>();
    k_packB2_csr<<<(E_EDGES + 255) / 256, 256>>>(Wq, Wk, Wv, Ws, bq, bk, bv, bs, ei);

    // g = (x @ W_gcn) * dinv[row]
    k_mmagemm<0><<<dim3(M_TILES, 2), 256>>>(x);

    k_agg<<<N_NODES, 128>>>(b_gcn);

    // qkvs = h @ Wcat + bcat
    k_mmagemm<1><<<dim3(M_TILES, 4), 256>>>(nullptr);

    k_alpha<<<(E_EDGES + 7) / 8, 256>>>(ei);
    k_stats<<<STAT_BLOCKS, 256>>>();
    k_finalize<<<1, STAT_BLOCKS>>>();
    k_out<<<N_NODES, D_OUT>>>(out);
}

// round 15
// speedup vs baseline: 1.1941x; 1.1941x over previous
#include <cuda_runtime.h>
#include <cuda_bf16.h>
#include <math.h>
#include <stdint.h>

#define N_NODES 20000
#define E_EDGES 320000
#define F_IN    1024
#define H_MID   256
#define D_OUT   128
#define QKVS    512
#define STAT_BLOCKS 256
#define M_TILES ((N_NODES + 127) / 128)

// ---------------- scratch (static device globals; no allocations) ----------------
// zero-initialized at module load; g_degcnt/g_fill self-reset across graph replays.
__device__ __align__(16) float  g_g[(size_t)N_NODES * H_MID];
__device__ __align__(16) float  g_qkvs[(size_t)N_NODES * QKVS];
__device__ __align__(16) float  g_alpha[E_EDGES];
__device__ float  g_dinv[N_NODES];
__device__ int    g_degcnt[N_NODES];
__device__ int    g_fill[N_NODES];
__device__ int    g_rowptr[N_NODES + 1];
__device__ int    g_csrc[E_EDGES];
__device__ int    g_ceid[E_EDGES];
__device__ double g_part[STAT_BLOCKS][2];
__device__ float  g_stats[2];
__device__ __align__(16) float  g_bcat[QKVS];
// bf16 split operands
__device__ __align__(16) __nv_bfloat16 g_B1hi[(size_t)H_MID * F_IN];   // W_gcn^T [256][1024]
__device__ __align__(16) __nv_bfloat16 g_B1lo[(size_t)H_MID * F_IN];
__device__ __align__(16) __nv_bfloat16 g_Hhi[(size_t)N_NODES * H_MID]; // split h
__device__ __align__(16) __nv_bfloat16 g_Hlo[(size_t)N_NODES * H_MID];
__device__ __align__(16) __nv_bfloat16 g_B2hi[(size_t)QKVS * H_MID];   // Wcat^T [512][256]
__device__ __align__(16) __nv_bfloat16 g_B2lo[(size_t)QKVS * H_MID];

// ---------------- helpers ----------------
__device__ __forceinline__ uint32_t smem_u32(const void* p) {
    uint32_t a;
    asm("{ .reg .u64 t; cvta.to.shared.u64 t, %1; cvt.u32.u64 %0, t; }" : "=r"(a) : "l"(p));
    return a;
}
__device__ __forceinline__ void mma16816(float* c, const uint32_t* a, const uint32_t* b) {
    asm volatile(
        "mma.sync.aligned.m16n8k16.row.col.f32.bf16.bf16.f32 "
        "{%0,%1,%2,%3}, {%4,%5,%6,%7}, {%8,%9}, {%0,%1,%2,%3};"
        : "+f"(c[0]), "+f"(c[1]), "+f"(c[2]), "+f"(c[3])
        : "r"(a[0]), "r"(a[1]), "r"(a[2]), "r"(a[3]), "r"(b[0]), "r"(b[1]));
}
__device__ __forceinline__ void ldm4(uint32_t* r, uint32_t addr) {
    asm volatile("ldmatrix.sync.aligned.m8n8.x4.shared.b16 {%0,%1,%2,%3}, [%4];"
        : "=r"(r[0]), "=r"(r[1]), "=r"(r[2]), "=r"(r[3]) : "r"(addr) : "memory");
}
__device__ __forceinline__ void split2(float a, float b, __nv_bfloat162& h, __nv_bfloat162& l) {
    __nv_bfloat16 ha = __float2bfloat16_rn(a);
    __nv_bfloat16 hb = __float2bfloat16_rn(b);
    h.x = ha; h.y = hb;
    l.x = __float2bfloat16_rn(a - __bfloat162float(ha));
    l.y = __float2bfloat16_rn(b - __bfloat162float(hb));
}
__device__ __forceinline__ void splitpack(float a, float b, uint32_t& hw, uint32_t& lw) {
    __nv_bfloat162 h, l;
    split2(a, b, h, l);
    hw = *(uint32_t*)&h;
    lw = *(uint32_t*)&l;
}

// ---------------- merged: W_gcn conversion + degree histogram ----------------
__global__ void k_convBW_hist(const float* __restrict__ Wg, const int* __restrict__ ei) {
    int idx = blockIdx.x * blockDim.x + threadIdx.x;
    if (idx < H_MID * F_IN) {
        int n = idx >> 10, k = idx & 1023;
        float v = Wg[(size_t)k * H_MID + n];
        __nv_bfloat16 h = __float2bfloat16_rn(v);
        g_B1hi[idx] = h;
        g_B1lo[idx] = __float2bfloat16_rn(v - __bfloat162float(h));
    }
    if (idx < E_EDGES) atomicAdd(&g_degcnt[ei[E_EDGES + idx]], 1);
}

// single-block scan; computes dinv; self-resets degcnt
__global__ void k_scan() {
    const int n = N_NODES;
    const int PER = 20;
    __shared__ int wsum[32];
    int tid = threadIdx.x, lane = tid & 31, wid = tid >> 5;
    int start = tid * PER;
    int cnt[PER];
    int local = 0;
#pragma unroll
    for (int u = 0; u < PER; u++) {
        int i = start + u;
        int c = (i < n) ? g_degcnt[i] : 0;
        cnt[u] = c; local += c;
        if (i < n) g_degcnt[i] = 0;
    }
    int v = local;
#pragma unroll
    for (int d = 1; d < 32; d <<= 1) { int t = __shfl_up_sync(0xffffffffu, v, d); if (lane >= d) v += t; }
    if (lane == 31) wsum[wid] = v;
    __syncthreads();
    if (wid == 0) {
        int w = wsum[lane];
#pragma unroll
        for (int d = 1; d < 32; d <<= 1) { int t = __shfl_up_sync(0xffffffffu, w, d); if (lane >= d) w += t; }
        wsum[lane] = w;
    }
    __syncthreads();
    int excl = (v - local) + (wid > 0 ? wsum[wid - 1] : 0);
    int run = excl;
#pragma unroll
    for (int u = 0; u < PER; u++) {
        int i = start + u;
        if (i < n) {
            g_rowptr[i] = run;
            g_dinv[i] = rsqrtf((float)(cnt[u] + 1));
        }
        run += cnt[u];
    }
    if (tid == 1023) g_rowptr[n] = run;
}

// ---------------- merged: QKVS weight pack + CSR scatter ----------------
__global__ void k_packB2_csr(const float* __restrict__ Wq, const float* __restrict__ Wk,
                             const float* __restrict__ Wv, const float* __restrict__ Ws,
                             const float* __restrict__ bq, const float* __restrict__ bk,
                             const float* __restrict__ bv, const float* __restrict__ bs,
                             const int* __restrict__ ei) {
    int idx = blockIdx.x * blockDim.x + threadIdx.x;
    if (idx < QKVS * H_MID) {
        int n = idx >> 8, k = idx & 255;
        int w = n >> 7, c = n & 127;
        const float* W = (w == 0) ? Wq : (w == 1) ? Wk : (w == 2) ? Wv : Ws;
        float v = W[(size_t)k * D_OUT + c];
        __nv_bfloat16 h = __float2bfloat16_rn(v);
        g_B2hi[idx] = h;
        g_B2lo[idx] = __float2bfloat16_rn(v - __bfloat162float(h));
        if (idx < QKVS) {
            int nn = idx, ww = nn >> 7, cc = nn & 127;
            const float* b = (ww == 0) ? bq : (ww == 1) ? bk : (ww == 2) ? bv : bs;
            g_bcat[nn] = b[cc];
        }
    }
    if (idx < E_EDGES) {
        int s = ei[idx];
        int d = ei[E_EDGES + idx];
        int pos = g_rowptr[d] + atomicAdd(&g_fill[d], 1);
        g_csrc[pos] = s;
        g_ceid[pos] = idx;
    }
}

// ---------------- split-bf16 GEMM: 128x128, distance-2 prefetch, static reg sets ----------------
// MODE 0: g_g = (x @ W_gcn) * dinv[row]; A = fp32 x split in store phase; grid (157,2)
// MODE 1: g_qkvs = h @ Wcat + bcat; A = g_Hhi/Hlo; grid (157,4)
#define SPAD 24

template <int MODE>
__global__ __launch_bounds__(256)
void k_mmagemm(const float* __restrict__ X) {
    const int K_TOT = (MODE == 0) ? F_IN : H_MID;
    const __nv_bfloat16* Bhi = (MODE == 0) ? g_B1hi : g_B2hi;
    const __nv_bfloat16* Blo = (MODE == 0) ? g_B1lo : g_B2lo;

    __shared__ __align__(16) __nv_bfloat16 sAh[128 * SPAD], sAl[128 * SPAD];
    __shared__ __align__(16) __nv_bfloat16 sBh[128 * SPAD], sBl[128 * SPAD];

    int tid = threadIdx.x, wid = tid >> 5, lane = tid & 31;
    int m0 = blockIdx.x * 128, n0 = blockIdx.y * 128;
    int wm = wid & 3, wn = wid >> 2;          // warp grid 4(m) x 2(n); warp tile 32x64

    int lrow = tid >> 1, lhalf = (tid & 1) << 3;
    const int NCH = K_TOT / 16;               // 64 or 16 (even)
    int arow = m0 + lrow;
    bool aok = arow < N_NODES;
    const float* pX = X + (size_t)arow * K_TOT + lhalf;               // MODE 0
    const __nv_bfloat16* pAh = g_Hhi + (size_t)arow * K_TOT + lhalf;  // MODE 1
    const __nv_bfloat16* pAl = g_Hlo + (size_t)arow * K_TOT + lhalf;
    const __nv_bfloat16* pBh = Bhi + (size_t)(n0 + lrow) * K_TOT + lhalf;
    const __nv_bfloat16* pBl = Blo + (size_t)(n0 + lrow) * K_TOT + lhalf;

    // two STATICALLY NAMED register prefetch sets (distance 2) — no dynamic indexing
    uint4 z4 = make_uint4(0, 0, 0, 0);
    float4 z4f = make_float4(0.f, 0.f, 0.f, 0.f);
    float4 xa0 = z4f, xb0 = z4f, xa1 = z4f, xb1 = z4f;      // MODE 0
    uint4 vah0 = z4, val0 = z4, vah1 = z4, val1 = z4;       // MODE 1
    uint4 vbh0 = z4, vbl0 = z4, vbh1 = z4, vbl1 = z4;

    // preload chunk 0 -> set 0, chunk 1 -> set 1
    if (MODE == 0) {
        if (aok) {
            xa0 = *(const float4*)pX;        xb0 = *(const float4*)(pX + 4);
            xa1 = *(const float4*)(pX + 16); xb1 = *(const float4*)(pX + 20);
        }
    } else {
        if (aok) {
            vah0 = *(const uint4*)pAh;        val0 = *(const uint4*)pAl;
            vah1 = *(const uint4*)(pAh + 16); val1 = *(const uint4*)(pAl + 16);
        }
    }
    vbh0 = *(const uint4*)pBh;        vbl0 = *(const uint4*)pBl;
    vbh1 = *(const uint4*)(pBh + 16); vbl1 = *(const uint4*)(pBl + 16);

    float acc[2][8][4];
#pragma unroll
    for (int a = 0; a < 2; a++)
#pragma unroll
        for (int b = 0; b < 8; b++)
#pragma unroll
            for (int c = 0; c < 4; c++) acc[a][b][c] = 0.f;

    uint32_t baseAh = smem_u32(sAh), baseAl = smem_u32(sAl);
    uint32_t baseBh = smem_u32(sBh), baseBl = smem_u32(sBl);
    int soff = lrow * SPAD + lhalf;

    int g8 = lane >> 3, w8 = lane & 7;
    uint32_t a_off = (uint32_t)((((((g8 & 1) << 3) + w8) + wm * 32) * SPAD + ((g8 >> 1) << 3)) * 2);
    uint32_t b_off = (uint32_t)((((((g8 >> 1) << 3) + w8) + wn * 64) * SPAD + ((g8 & 1) << 3)) * 2);

    // compute on whatever is currently staged in smem
    auto compute = [&]() {
        uint32_t ah[2][4], al[2][4], bh[4][4], bl[4][4];
#pragma unroll
        for (int mb = 0; mb < 2; mb++) {
            ldm4(ah[mb], baseAh + a_off + mb * 16 * SPAD * 2);
            ldm4(al[mb], baseAl + a_off + mb * 16 * SPAD * 2);
        }
#pragma unroll
        for (int q = 0; q < 4; q++) {
            ldm4(bh[q], baseBh + b_off + q * 16 * SPAD * 2);
            ldm4(bl[q], baseBl + b_off + q * 16 * SPAD * 2);
        }
#pragma unroll
        for (int mb = 0; mb < 2; mb++)
#pragma unroll
            for (int q = 0; q < 4; q++)
#pragma unroll
                for (int hh = 0; hh < 2; hh++) {
                    float* ca = acc[mb][q * 2 + hh];
                    mma16816(ca, ah[mb], &bh[q][hh * 2]);
                    mma16816(ca, al[mb], &bh[q][hh * 2]);
                    mma16816(ca, ah[mb], &bl[q][hh * 2]);
                }
    };

    for (int c = 0; c < NCH; c += 2) {
        // ===== chunk c (set 0) =====
        if (MODE == 0) {
            uint4 hw, lw;
            splitpack(xa0.x, xa0.y, hw.x, lw.x);
            splitpack(xa0.z, xa0.w, hw.y, lw.y);
            splitpack(xb0.x, xb0.y, hw.z, lw.z);
            splitpack(xb0.z, xb0.w, hw.w, lw.w);
            *(uint4*)&sAh[soff] = hw;
            *(uint4*)&sAl[soff] = lw;
        } else {
            *(uint4*)&sAh[soff] = vah0;
            *(uint4*)&sAl[soff] = val0;
        }
        *(uint4*)&sBh[soff] = vbh0;
        *(uint4*)&sBl[soff] = vbl0;
        __syncthreads();
        if (c + 2 < NCH) {                     // preload chunk c+2 -> set 0
            int k0 = (c + 2) * 16;
            if (MODE == 0) {
                if (aok) { xa0 = *(const float4*)(pX + k0); xb0 = *(const float4*)(pX + k0 + 4); }
            } else {
                if (aok) { vah0 = *(const uint4*)(pAh + k0); val0 = *(const uint4*)(pAl + k0); }
            }
            vbh0 = *(const uint4*)(pBh + k0);
            vbl0 = *(const uint4*)(pBl + k0);
        }
        compute();
        __syncthreads();

        // ===== chunk c+1 (set 1) =====
        if (MODE == 0) {
            uint4 hw, lw;
            splitpack(xa1.x, xa1.y, hw.x, lw.x);
            splitpack(xa1.z, xa1.w, hw.y, lw.y);
            splitpack(xb1.x, xb1.y, hw.z, lw.z);
            splitpack(xb1.z, xb1.w, hw.w, lw.w);
            *(uint4*)&sAh[soff] = hw;
            *(uint4*)&sAl[soff] = lw;
        } else {
            *(uint4*)&sAh[soff] = vah1;
            *(uint4*)&sAl[soff] = val1;
        }
        *(uint4*)&sBh[soff] = vbh1;
        *(uint4*)&sBl[soff] = vbl1;
        __syncthreads();
        if (c + 3 < NCH) {                     // preload chunk c+3 -> set 1
            int k0 = (c + 3) * 16;
            if (MODE == 0) {
                if (aok) { xa1 = *(const float4*)(pX + k0); xb1 = *(const float4*)(pX + k0 + 4); }
            } else {
                if (aok) { vah1 = *(const uint4*)(pAh + k0); val1 = *(const uint4*)(pAl + k0); }
            }
            vbh1 = *(const uint4*)(pBh + k0);
            vbl1 = *(const uint4*)(pBl + k0);
        }
        compute();
        __syncthreads();
    }

    const int CS = (MODE == 0) ? H_MID : QKVS;
    float* Cp = (MODE == 0) ? g_g : g_qkvs;
#pragma unroll
    for (int mb = 0; mb < 2; mb++) {
        int rbase = m0 + wm * 32 + mb * 16 + (lane >> 2);
#pragma unroll
        for (int hf = 0; hf < 2; hf++) {
            int r = rbase + hf * 8;
            if (r >= N_NODES) continue;
            float rs = (MODE == 0) ? g_dinv[r] : 1.f;
#pragma unroll
            for (int n8 = 0; n8 < 8; n8++) {
                int col = n0 + wn * 64 + n8 * 8 + ((lane & 3) << 1);
                float v0 = acc[mb][n8][hf * 2 + 0];
                float v1 = acc[mb][n8][hf * 2 + 1];
                if (MODE == 0) { v0 *= rs; v1 *= rs; }
                else { v0 += g_bcat[col]; v1 += g_bcat[col + 1]; }
                float2 o; o.x = v0; o.y = v1;
                *(float2*)(Cp + (size_t)r * CS + col) = o;
            }
        }
    }
}

// ---------------- GCN aggregation: float2/thread, 8-way unroll, split write ----------------
__global__ __launch_bounds__(128)
void k_agg(const float* __restrict__ b_gcn) {
    int i = blockIdx.x;
    int f = threadIdx.x;
    if (f == 0) g_fill[i] = 0;                 // reset for next replay
    const float2* G = (const float2*)g_g;
    float2 a0 = G[(size_t)i * 128 + f];        // self loop
    float2 a1 = make_float2(0.f, 0.f), a2 = a1, a3 = a1;
    float2 a4 = a1, a5 = a1, a6 = a1, a7 = a1;
    __shared__ int sj[128];
    int s0 = g_rowptr[i], e0 = g_rowptr[i + 1];
    for (int base = s0; base < e0; base += 128) {
        int cnt = min(128, e0 - base);
        if (f < cnt) sj[f] = g_csrc[base + f];
        __syncthreads();
        int p = 0;
        for (; p + 8 <= cnt; p += 8) {
            float2 v0 = G[(size_t)sj[p + 0] * 128 + f];
            float2 v1 = G[(size_t)sj[p + 1] * 128 + f];
            float2 v2 = G[(size_t)sj[p + 2] * 128 + f];
            float2 v3 = G[(size_t)sj[p + 3] * 128 + f];
            float2 v4 = G[(size_t)sj[p + 4] * 128 + f];
            float2 v5 = G[(size_t)sj[p + 5] * 128 + f];
            float2 v6 = G[(size_t)sj[p + 6] * 128 + f];
            float2 v7 = G[(size_t)sj[p + 7] * 128 + f];
            a0.x += v0.x; a0.y += v0.y;
            a1.x += v1.x; a1.y += v1.y;
            a2.x += v2.x; a2.y += v2.y;
            a3.x += v3.x; a3.y += v3.y;
            a4.x += v4.x; a4.y += v4.y;
            a5.x += v5.x; a5.y += v5.y;
            a6.x += v6.x; a6.y += v6.y;
            a7.x += v7.x; a7.y += v7.y;
        }
        for (; p + 4 <= cnt; p += 4) {
            float2 v0 = G[(size_t)sj[p + 0] * 128 + f];
            float2 v1 = G[(size_t)sj[p + 1] * 128 + f];
            float2 v2 = G[(size_t)sj[p + 2] * 128 + f];
            float2 v3 = G[(size_t)sj[p + 3] * 128 + f];
            a0.x += v0.x; a0.y += v0.y;
            a1.x += v1.x; a1.y += v1.y;
            a2.x += v2.x; a2.y += v2.y;
            a3.x += v3.x; a3.y += v3.y;
        }
        for (; p < cnt; p++) {
            float2 v = G[(size_t)sj[p] * 128 + f];
            a0.x += v.x; a0.y += v.y;
        }
        __syncthreads();
    }
    float di = g_dinv[i];
    float2 bb = ((const float2*)b_gcn)[f];
    float vx = di * (((a0.x + a1.x) + (a2.x + a3.x)) + ((a4.x + a5.x) + (a6.x + a7.x))) + bb.x;
    float vy = di * (((a0.y + a1.y) + (a2.y + a3.y)) + ((a4.y + a5.y) + (a6.y + a7.y))) + bb.y;
    vx = (vx >= 0.f) ? vx : 0.01f * vx;
    vy = (vy >= 0.f) ? vy : 0.01f * vy;
    __nv_bfloat162 h, l;
    split2(vx, vy, h, l);
    ((__nv_bfloat162*)g_Hhi)[(size_t)i * 128 + f] = h;
    ((__nv_bfloat162*)g_Hlo)[(size_t)i * 128 + f] = l;
}

// ---------------- attention logits (warp per edge) ----------------
__global__ __launch_bounds__(256)
void k_alpha(const int* __restrict__ ei) {
    int warp = threadIdx.x >> 5, lane = threadIdx.x & 31;
    int e = blockIdx.x * 8 + warp;
    if (e >= E_EDGES) return;
    int s = ei[e], d = ei[E_EDGES + e];
    const float4* q = (const float4*)(g_qkvs + (size_t)d * QKVS);
    const float4* k = (const float4*)(g_qkvs + (size_t)s * QKVS + D_OUT);
    float4 a = q[lane], b = k[lane];
    float p = a.x * b.x + a.y * b.y + a.z * b.z + a.w * b.w;
#pragma unroll
    for (int o = 16; o; o >>= 1) p += __shfl_xor_sync(0xffffffffu, p, o);
    if (lane == 0) g_alpha[e] = p * 0.08838834764831845f;
}

__global__ __launch_bounds__(256)
void k_stats() {
    double s = 0.0, s2 = 0.0;
    for (int i = blockIdx.x * blockDim.x + threadIdx.x; i < E_EDGES; i += STAT_BLOCKS * 256) {
        double a = (double)g_alpha[i];
        s += a; s2 += a * a;
    }
#pragma unroll
    for (int o = 16; o; o >>= 1) {
        s  += __shfl_down_sync(0xffffffffu, s,  o);
        s2 += __shfl_down_sync(0xffffffffu, s2, o);
    }
    __shared__ double ws[8], ws2[8];
    int lane = threadIdx.x & 31, wid = threadIdx.x >> 5;
    if (lane == 0) { ws[wid] = s; ws2[wid] = s2; }
    __syncthreads();
    if (threadIdx.x == 0) {
        double ts = 0.0, ts2 = 0.0;
        for (int w = 0; w < 8; w++) { ts += ws[w]; ts2 += ws2[w]; }
        g_part[blockIdx.x][0] = ts;
        g_part[blockIdx.x][1] = ts2;
    }
}

__global__ __launch_bounds__(STAT_BLOCKS)
void k_finalize() {
    int t = threadIdx.x;
    double s = g_part[t][0], s2 = g_part[t][1];
#pragma unroll
    for (int o = 16; o; o >>= 1) {
        s  += __shfl_down_sync(0xffffffffu, s,  o);
        s2 += __shfl_down_sync(0xffffffffu, s2, o);
    }
    __shared__ double ws[8], ws2[8];
    int lane = t & 31, wid = t >> 5;
    if (lane == 0) { ws[wid] = s; ws2[wid] = s2; }
    __syncthreads();
    if (t == 0) {
        double ts = 0.0, ts2 = 0.0;
        for (int w = 0; w < STAT_BLOCKS / 32; w++) { ts += ws[w]; ts2 += ws2[w]; }
        double En = (double)E_EDGES;
        double mean = ts / En;
        double var = (ts2 - En * mean * mean) / (En - 1.0);   // ddof=1
        g_stats[0] = (float)mean;
        g_stats[1] = (float)(3.0 / sqrt(var));                // SCALE_PARAM/std
    }
}

// ---------------- output: 8-way MLP unroll ----------------
__global__ __launch_bounds__(D_OUT)
void k_out(float* __restrict__ out) {
    int i = blockIdx.x;
    int f = threadIdx.x;
    float mean = g_stats[0], sc = g_stats[1];
    float a0 = g_qkvs[(size_t)i * QKVS + 384 + f];   // skip s = h@Ws + bs
    float a1 = 0.f, a2 = 0.f, a3 = 0.f, a4 = 0.f, a5 = 0.f, a6 = 0.f, a7 = 0.f;
    __shared__ int   sj[D_OUT];
    __shared__ float sa[D_OUT];
    int s0 = g_rowptr[i], e0 = g_rowptr[i + 1];
    for (int base = s0; base < e0; base += D_OUT) {
        int cnt = min(D_OUT, e0 - base);
        if (f < cnt) {
            sj[f] = g_csrc[base + f];
            float a = (g_alpha[g_ceid[base + f]] - mean) * sc;
            sa[f] = 1.0f / (1.0f + expf(-a));
        }
        __syncthreads();
        int p = 0;
        for (; p + 8 <= cnt; p += 8) {
            float v0 = g_qkvs[(size_t)sj[p + 0] * QKVS + 256 + f];
            float v1 = g_qkvs[(size_t)sj[p + 1] * QKVS + 256 + f];
            float v2 = g_qkvs[(size_t)sj[p + 2] * QKVS + 256 + f];
            float v3 = g_qkvs[(size_t)sj[p + 3] * QKVS + 256 + f];
            float v4 = g_qkvs[(size_t)sj[p + 4] * QKVS + 256 + f];
            float v5 = g_qkvs[(size_t)sj[p + 5] * QKVS + 256 + f];
            float v6 = g_qkvs[(size_t)sj[p + 6] * QKVS + 256 + f];
            float v7 = g_qkvs[(size_t)sj[p + 7] * QKVS + 256 + f];
            a0 += v0 * sa[p + 0];
            a1 += v1 * sa[p + 1];
            a2 += v2 * sa[p + 2];
            a3 += v3 * sa[p + 3];
            a4 += v4 * sa[p + 4];
            a5 += v5 * sa[p + 5];
            a6 += v6 * sa[p + 6];
            a7 += v7 * sa[p + 7];
        }
        for (; p + 4 <= cnt; p += 4) {
            float v0 = g_qkvs[(size_t)sj[p + 0] * QKVS + 256 + f];
            float v1 = g_qkvs[(size_t)sj[p + 1] * QKVS + 256 + f];
            float v2 = g_qkvs[(size_t)sj[p + 2] * QKVS + 256 + f];
            float v3 = g_qkvs[(size_t)sj[p + 3] * QKVS + 256 + f];
            a0 += v0 * sa[p + 0];
            a1 += v1 * sa[p + 1];
            a2 += v2 * sa[p + 2];
            a3 += v3 * sa[p + 3];
        }
        for (; p < cnt; p++)
            a0 += g_qkvs[(size_t)sj[p] * QKVS + 256 + f] * sa[p];
        __syncthreads();
    }
    out[(size_t)i * D_OUT + f] = ((a0 + a1) + (a2 + a3)) + ((a4 + a5) + (a6 + a7));
}

// ---------------- launch ----------------
extern "C" void kernel_launch(void* const* d_in, const int* in_sizes, int n_in,
                              void* d_out, int out_size) {
    (void)in_sizes; (void)n_in; (void)out_size;
    const float* x     = (const float*)d_in[0];
    const int*   ei    = (const int*)d_in[1];
    const float* W_gcn = (const float*)d_in[2];
    const float* b_gcn = (const float*)d_in[3];
    const float* Wq = (const float*)d_in[4],  *bq = (const float*)d_in[5];
    const float* Wk = (const float*)d_in[6],  *bk = (const float*)d_in[7];
    const float* Wv = (const float*)d_in[8],  *bv = (const float*)d_in[9];
    const float* Ws = (const float*)d_in[10], *bs = (const float*)d_in[11];
    float* out = (float*)d_out;

    k_convBW_hist<<<(E_EDGES + 255) / 256, 256>>>(W_gcn, ei);
    k_scan<<<1, 1024>>>();
    k_packB2_csr<<<(E_EDGES + 255) / 256, 256>>>(Wq, Wk, Wv, Ws, bq, bk, bv, bs, ei);

    // g = (x @ W_gcn) * dinv[row]
    k_mmagemm<0><<<dim3(M_TILES, 2), 256>>>(x);

    k_agg<<<N_NODES, 128>>>(b_gcn);

    // qkvs = h @ Wcat + bcat
    k_mmagemm<1><<<dim3(M_TILES, 4), 256>>>(nullptr);

    k_alpha<<<(E_EDGES + 7) / 8, 256>>>(ei);
    k_stats<<<STAT_BLOCKS, 256>>>();
    k_finalize<<<1, STAT_BLOCKS>>>();
    k_out<<<N_NODES, D_OUT>>>(out);
}